// round 6
// baseline (speedup 1.0000x reference)
#include <cuda_runtime.h>
#include <cuda_fp16.h>
#include <cstdint>

// Inputs (metadata order):
// 0: x [N,64] f32   1: node_batch [N] int32-or-int64 (sorted)  2: global_attr [B,3] f32
// 3: Wg [3,64] f32  4: bg [64] f32  5: Wn [128,64] f32  6: bn [64] f32
// 7: Wa [64,1] f32  8: ba [1] f32
// out: w [N,1] f32   (holds score s between k_main and k_soft)

#define BMAX 8192
#define BMSK (BMAX - 1)

__device__ float d_c[BMAX * 64];               // c[b] = (ga_b@Wg+bg) @ Wn[64:] + bn
__device__ __align__(16) __half d_Bh[64 * 64]; // Wn[0:64] preconverted to f16
__device__ int   d_start[BMAX];                // zero-init BSS; written once per nonempty seg
__device__ int   d_end[BMAX];
__device__ int   d_is64;

// ---------------- helpers ----------------

__device__ __forceinline__ uint32_t s2u(const void* p) {
    return (uint32_t)__cvta_generic_to_shared(p);
}
__device__ __forceinline__ void ldm_x4(uint32_t* r, uint32_t addr) {
    asm volatile("ldmatrix.sync.aligned.m8n8.x4.shared.b16 {%0,%1,%2,%3}, [%4];"
                 : "=r"(r[0]), "=r"(r[1]), "=r"(r[2]), "=r"(r[3]) : "r"(addr));
}
__device__ __forceinline__ void ldm_x4t(uint32_t* r, uint32_t addr) {
    asm volatile("ldmatrix.sync.aligned.m8n8.x4.trans.shared.b16 {%0,%1,%2,%3}, [%4];"
                 : "=r"(r[0]), "=r"(r[1]), "=r"(r[2]), "=r"(r[3]) : "r"(addr));
}
__device__ __forceinline__ void mma16816(float* d, const uint32_t* a, const uint32_t* b) {
    asm volatile("mma.sync.aligned.m16n8k16.row.col.f32.f16.f16.f32 "
                 "{%0,%1,%2,%3}, {%4,%5,%6,%7}, {%8,%9}, {%0,%1,%2,%3};"
                 : "+f"(d[0]), "+f"(d[1]), "+f"(d[2]), "+f"(d[3])
                 : "r"(a[0]), "r"(a[1]), "r"(a[2]), "r"(a[3]), "r"(b[0]), "r"(b[1]));
}
__device__ __forceinline__ int seg_at(const void* nbraw, int i) {
    if (d_is64) return ((int)((const long long*)nbraw)[i]) & BMSK;
    return ((const int*)nbraw)[i] & BMSK;
}
__device__ __forceinline__ float softplusf(float z) {
    float az = fabsf(z);
    float t = az * -1.4426950408889634f;
    float p, l;
    asm("ex2.approx.ftz.f32 %0, %1;" : "=f"(p) : "f"(t));
    float op = 1.0f + p;
    asm("lg2.approx.ftz.f32 %0, %1;" : "=f"(l) : "f"(op));
    return fmaxf(z, 0.0f) + 0.6931471805599453f * l;
}
__device__ __forceinline__ float exp2a(float t) {
    float e;
    asm("ex2.approx.ftz.f32 %0, %1;" : "=f"(e) : "f"(t));
    return e;
}

// ---------------- kernel 0: detect node_batch dtype ----------------
__global__ void k_detect(const int* __restrict__ p32, int n) {
    int last = n - 1;
    if (!(last & 1)) last--;
    int acc = 0;
    for (int k = 0; k < 8; k++) {
        int idx = last - 2 * k;
        if (idx >= 1) acc |= p32[idx];
    }
    d_is64 = (acc == 0) ? 1 : 0;
}

// ---------------- kernel 0b: preconvert B = Wn[0:64,:] to f16 ----------------
__global__ void k_prepB(const float* __restrict__ Wn) {
    for (int i = threadIdx.x; i < 4096; i += 256)
        d_Bh[i] = __float2half(Wn[i]);
}

// ---------------- kernel 1: per-graph c[b] ----------------
__global__ void k_graph(const float* __restrict__ ga, const float* __restrict__ Wg,
                        const float* __restrict__ bg, const float* __restrict__ Wn,
                        const float* __restrict__ bn) {
    int b = blockIdx.x;
    int j = threadIdx.x; // 0..63
    __shared__ float g[64];
    float a0 = ga[b * 3 + 0], a1 = ga[b * 3 + 1], a2 = ga[b * 3 + 2];
    g[j] = bg[j] + a0 * Wg[j] + a1 * Wg[64 + j] + a2 * Wg[128 + j];
    __syncthreads();
    float acc = bn[j];
#pragma unroll
    for (int i = 0; i < 64; i++)
        acc = fmaf(g[i], Wn[(64 + i) * 64 + j], acc);
    d_c[b * 64 + j] = acc;
}

// ---------------- kernel 1b: segment boundaries (no atomics; sorted ids) ----------------
__global__ void k_bound(const void* __restrict__ nbraw, int n) {
    int i = blockIdx.x * blockDim.x + threadIdx.x;
    if (i >= n) return;
    int v = seg_at(nbraw, i);
    if (i == 0) d_start[v] = 0;
    if (i + 1 == n) {
        d_end[v] = n;
    } else {
        int nx = seg_at(nbraw, i + 1);
        if (nx != v) { d_end[v] = i + 1; d_start[nx] = i + 1; }
    }
}

// ---------------- kernel 2: pipelined fused GEMM + softplus + dot -> s ----------------

#define LDA 72
#define LDB 72
#define TPC 4           // tiles (of 128 rows) per CTA

__global__ void __launch_bounds__(256)
k_main(const float* __restrict__ x, const void* __restrict__ nbraw,
       const float* __restrict__ Wa, const float* __restrict__ ba,
       float* __restrict__ out, int n) {
    __shared__ __align__(16) __half smB[64 * LDB];
    __shared__ __align__(16) __half smA[2][128 * LDA];
    __shared__ float sWa[64];
    __shared__ float sba;

    const int tid = threadIdx.x;
    const int wid = tid >> 5;
    const int lane = tid & 31;
    const int wbase = wid * 16;                 // 8 warps x 16 rows
    const int base = blockIdx.x * (TPC * 128);

    if (tid == 0) sba = ba[0];
    if (tid < 64) sWa[tid] = Wa[tid];

    // B from preconverted f16 global: 512 uint4
#pragma unroll
    for (int q = 0; q < 2; q++) {
        int j = q * 256 + tid;
        int row = j >> 3, c8 = (j & 7) * 8;
        uint4 v = reinterpret_cast<const uint4*>(d_Bh)[j];
        *reinterpret_cast<uint4*>(smB + row * LDB + c8) = v;
    }

    const int row_ = tid >> 1;                  // each thread: 1 row-half (32 floats)
    const int col_ = (tid & 1) * 32;

    // LDG + cvt one 128-row tile into regs (8 x uint2 = 8 x (4 halves))
    uint2 h[8];
    auto ldgcvt = [&](int t) {
        int g = base + t * 128 + row_;
        const float4* px = reinterpret_cast<const float4*>(x + (long long)g * 64 + col_);
#pragma unroll
        for (int it = 0; it < 8; it++) {
            float4 v = make_float4(0.f, 0.f, 0.f, 0.f);
            if (g < n) v = px[it];
            __half2 h0 = __floats2half2_rn(v.x, v.y);
            __half2 h1 = __floats2half2_rn(v.z, v.w);
            h[it].x = *reinterpret_cast<uint32_t*>(&h0);
            h[it].y = *reinterpret_cast<uint32_t*>(&h1);
        }
    };
    auto stsA = [&](int buf) {
        __half* dst = smA[buf] + row_ * LDA + col_;
#pragma unroll
        for (int it = 0; it < 8; it++)
            *reinterpret_cast<uint2*>(dst + it * 4) = h[it];
    };

    ldgcvt(0);
    stsA(0);
    if (base + 128 < n) ldgcvt(1);
    __syncthreads();

    const uint32_t aB = s2u(smB);

    for (int t = 0; t < TPC; t++) {
        const int r0 = base + t * 128;
        if (r0 >= n) break;

        // ---- MMA on smA[t&1]: rows [wbase,wbase+16) x cols [0,64), K=64 ----
        const uint32_t aA = s2u(smA[t & 1]);
        float d[8][4];
#pragma unroll
        for (int nt = 0; nt < 8; nt++)
#pragma unroll
            for (int q = 0; q < 4; q++) d[nt][q] = 0.f;

#pragma unroll
        for (int kk = 0; kk < 4; kk++) {
            uint32_t a[4];
            {
                uint32_t addr = aA + ((wbase + (lane & 15)) * LDA +
                                      kk * 16 + ((lane >> 4) << 3)) * 2;
                ldm_x4(a, addr);
            }
            uint32_t b[16];
#pragma unroll
            for (int np = 0; np < 4; np++) {
                uint32_t addr = aB + ((kk * 16 + (lane & 15)) * LDB +
                                      np * 16 + ((lane >> 4) << 3)) * 2;
                ldm_x4t(b + np * 4, addr);
            }
#pragma unroll
            for (int nt = 0; nt < 8; nt++)
                mma16816(d[nt], a, b + nt * 2);
        }

        // ---- stage t+1 into the other buffer, prefetch t+2 ----
        if (t + 1 < TPC && r0 + 128 < n) stsA((t + 1) & 1);
        if (t + 2 < TPC && r0 + 256 < n) ldgcvt(t + 2);

        // ---- epilogue: +c[seg], softplus, dot Wa ----
        const int g8 = lane >> 2;
        const int l3 = lane & 3;
        float2 wv[8];
#pragma unroll
        for (int nt = 0; nt < 8; nt++)
            wv[nt] = *reinterpret_cast<const float2*>(sWa + nt * 8 + 2 * l3);

#pragma unroll
        for (int hh = 0; hh < 2; hh++) {
            int gr = r0 + wbase + hh * 8 + g8;
            int sg = (gr < n) ? seg_at(nbraw, gr) : 0;
            const float2* cp = reinterpret_cast<const float2*>(d_c + sg * 64);
            float acc = 0.f;
#pragma unroll
            for (int nt = 0; nt < 8; nt++) {
                float2 cc = __ldg(cp + nt * 4 + l3);
                float v0 = d[nt][hh * 2 + 0] + cc.x;
                float v1 = d[nt][hh * 2 + 1] + cc.y;
                acc = fmaf(wv[nt].x, softplusf(v0), acc);
                acc = fmaf(wv[nt].y, softplusf(v1), acc);
            }
            acc += __shfl_xor_sync(0xFFFFFFFFu, acc, 1);
            acc += __shfl_xor_sync(0xFFFFFFFFu, acc, 2);
            if (l3 == 0 && gr < n) out[gr] = acc + sba;
        }

        __syncthreads();   // STS(t+1) visible; all MMA(t) reads done
    }
}

// ---------------- kernel 3: warp-per-graph softmax ----------------

#define CH 12   // register-cached elements per lane (covers count <= 384)

__global__ void __launch_bounds__(256)
k_soft(float* __restrict__ out, int n, int B) {
    const int b = blockIdx.x * 8 + (threadIdx.x >> 5);
    if (b >= B) return;
    const int lane = threadIdx.x & 31;
    int start = d_start[b];
    int end = d_end[b];
    if (end > n) end = n;
    if (start >= end) return;

    float vals[CH];
    float lm = __int_as_float(0xFF800000);
#pragma unroll
    for (int c = 0; c < CH; c++) {
        int i = start + lane + c * 32;
        if (i < end) { vals[c] = out[i]; lm = fmaxf(lm, vals[c]); }
    }
    for (int i = start + lane + CH * 32; i < end; i += 32)
        lm = fmaxf(lm, out[i]);

#pragma unroll
    for (int off = 16; off; off >>= 1)
        lm = fmaxf(lm, __shfl_xor_sync(0xFFFFFFFFu, lm, off));
    const float m = lm;

    float ls = 0.f;
#pragma unroll
    for (int c = 0; c < CH; c++) {
        int i = start + lane + c * 32;
        if (i < end) {
            float e = exp2a((vals[c] - m) * 1.4426950408889634f);
            vals[c] = e;
            ls += e;
        }
    }
    for (int i = start + lane + CH * 32; i < end; i += 32)
        ls += exp2a((out[i] - m) * 1.4426950408889634f);

#pragma unroll
    for (int off = 16; off; off >>= 1)
        ls += __shfl_xor_sync(0xFFFFFFFFu, ls, off);
    const float inv = 1.0f / (ls + 1e-16f);

#pragma unroll
    for (int c = 0; c < CH; c++) {
        int i = start + lane + c * 32;
        if (i < end) out[i] = vals[c] * inv;
    }
    for (int i = start + lane + CH * 32; i < end; i += 32)
        out[i] = exp2a((out[i] - m) * 1.4426950408889634f) * inv;
}

// ---------------- launch ----------------

extern "C" void kernel_launch(void* const* d_in, const int* in_sizes, int n_in,
                              void* d_out, int out_size) {
    const float* x = (const float*)d_in[0];
    const void* nb = d_in[1];
    const float* ga = (const float*)d_in[2];
    const float* Wg = (const float*)d_in[3];
    const float* bg = (const float*)d_in[4];
    const float* Wn = (const float*)d_in[5];
    const float* bn = (const float*)d_in[6];
    const float* Wa = (const float*)d_in[7];
    const float* ba = (const float*)d_in[8];
    float* out = (float*)d_out;

    int n = in_sizes[0] / 64;
    if (n > out_size) n = out_size;
    int B = in_sizes[2] / 3;
    if (B > BMAX) B = BMAX;

    int blk = (n + 255) / 256;

    k_detect<<<1, 1>>>((const int*)nb, n);
    k_prepB<<<1, 256>>>(Wn);
    k_graph<<<B, 64>>>(ga, Wg, bg, Wn, bn);
    k_bound<<<blk, 256>>>(nb, n);

    int ctas = (n + TPC * 128 - 1) / (TPC * 128);
    k_main<<<ctas, 256>>>(x, nb, Wa, ba, out, n);

    k_soft<<<(B + 7) / 8, 256>>>(out, n, B);
}

// round 7
// speedup vs baseline: 1.3805x; 1.3805x over previous
#include <cuda_runtime.h>
#include <cuda_fp16.h>
#include <cstdint>

// Inputs (metadata order):
// 0: x [N,64] f32   1: node_batch [N] int32-or-int64 (sorted)  2: global_attr [B,3] f32
// 3: Wg [3,64] f32  4: bg [64] f32  5: Wn [128,64] f32  6: bn [64] f32
// 7: Wa [64,1] f32  8: ba [1] f32
// out: w [N,1] f32   (holds score s between k_main and k_soft)

#define BMAX 8192
#define BMSK (BMAX - 1)

__device__ float d_c[BMAX * 64];               // c[b] = (ga_b@Wg+bg) @ Wn[64:] + bn
__device__ __align__(16) __half d_Bh[64 * 64]; // Wn[0:64] preconverted to f16
__device__ int   d_is64;

// ---------------- helpers ----------------

__device__ __forceinline__ uint32_t s2u(const void* p) {
    return (uint32_t)__cvta_generic_to_shared(p);
}
__device__ __forceinline__ void ldm_x4(uint32_t* r, uint32_t addr) {
    asm volatile("ldmatrix.sync.aligned.m8n8.x4.shared.b16 {%0,%1,%2,%3}, [%4];"
                 : "=r"(r[0]), "=r"(r[1]), "=r"(r[2]), "=r"(r[3]) : "r"(addr));
}
__device__ __forceinline__ void ldm_x4t(uint32_t* r, uint32_t addr) {
    asm volatile("ldmatrix.sync.aligned.m8n8.x4.trans.shared.b16 {%0,%1,%2,%3}, [%4];"
                 : "=r"(r[0]), "=r"(r[1]), "=r"(r[2]), "=r"(r[3]) : "r"(addr));
}
__device__ __forceinline__ void mma16816(float* d, const uint32_t* a, const uint32_t* b) {
    asm volatile("mma.sync.aligned.m16n8k16.row.col.f32.f16.f16.f32 "
                 "{%0,%1,%2,%3}, {%4,%5,%6,%7}, {%8,%9}, {%0,%1,%2,%3};"
                 : "+f"(d[0]), "+f"(d[1]), "+f"(d[2]), "+f"(d[3])
                 : "r"(a[0]), "r"(a[1]), "r"(a[2]), "r"(a[3]), "r"(b[0]), "r"(b[1]));
}
__device__ __forceinline__ int seg_at(const void* nbraw, int i) {
    if (d_is64) return ((int)((const long long*)nbraw)[i]) & BMSK;
    return ((const int*)nbraw)[i] & BMSK;
}
__device__ __forceinline__ float softplusf(float z) {
    float az = fabsf(z);
    float t = az * -1.4426950408889634f;
    float p, l;
    asm("ex2.approx.ftz.f32 %0, %1;" : "=f"(p) : "f"(t));
    float op = 1.0f + p;
    asm("lg2.approx.ftz.f32 %0, %1;" : "=f"(l) : "f"(op));
    return fmaxf(z, 0.0f) + 0.6931471805599453f * l;
}
__device__ __forceinline__ float exp2a(float t) {
    float e;
    asm("ex2.approx.ftz.f32 %0, %1;" : "=f"(e) : "f"(t));
    return e;
}

// ---------------- kernel 0: dtype detect + B preconvert ----------------
__global__ void k_prep(const int* __restrict__ p32, int n, const float* __restrict__ Wn) {
    if (threadIdx.x == 0) {
        int last = n - 1;
        if (!(last & 1)) last--;
        int acc = 0;
        for (int k = 0; k < 8; k++) {
            int idx = last - 2 * k;
            if (idx >= 1) acc |= p32[idx];
        }
        d_is64 = (acc == 0) ? 1 : 0;
    }
    for (int i = threadIdx.x; i < 4096; i += 256)
        d_Bh[i] = __float2half(Wn[i]);
}

// ---------------- kernel 1: per-graph c[b] ----------------
__global__ void k_graph(const float* __restrict__ ga, const float* __restrict__ Wg,
                        const float* __restrict__ bg, const float* __restrict__ Wn,
                        const float* __restrict__ bn) {
    int b = blockIdx.x;
    int j = threadIdx.x; // 0..63
    __shared__ float g[64];
    float a0 = ga[b * 3 + 0], a1 = ga[b * 3 + 1], a2 = ga[b * 3 + 2];
    g[j] = bg[j] + a0 * Wg[j] + a1 * Wg[64 + j] + a2 * Wg[128 + j];
    __syncthreads();
    float acc = bn[j];
#pragma unroll
    for (int i = 0; i < 64; i++)
        acc = fmaf(g[i], Wn[(64 + i) * 64 + j], acc);
    d_c[b * 64 + j] = acc;
}

// ---------------- kernel 2: pipelined fused GEMM + softplus + dot -> s ----------------

#define LDA 72
#define LDB 72
#define TPC 4           // tiles (of 128 rows) per CTA

__global__ void __launch_bounds__(256)
k_main(const float* __restrict__ x, const void* __restrict__ nbraw,
       const float* __restrict__ Wa, const float* __restrict__ ba,
       float* __restrict__ out, int n) {
    __shared__ __align__(16) __half smB[64 * LDB];
    __shared__ __align__(16) __half smA[2][128 * LDA];
    __shared__ float sWa[64];
    __shared__ float sba;

    const int tid = threadIdx.x;
    const int wid = tid >> 5;
    const int lane = tid & 31;
    const int wbase = wid * 16;                 // 8 warps x 16 rows
    const int base = blockIdx.x * (TPC * 128);

    if (tid == 0) sba = ba[0];
    if (tid < 64) sWa[tid] = Wa[tid];

    // B from preconverted f16 global: 512 uint4
#pragma unroll
    for (int q = 0; q < 2; q++) {
        int j = q * 256 + tid;
        int row = j >> 3, c8 = (j & 7) * 8;
        uint4 v = reinterpret_cast<const uint4*>(d_Bh)[j];
        *reinterpret_cast<uint4*>(smB + row * LDB + c8) = v;
    }

    // Coalesced f4 mapping: f4 = it*256+tid -> row=f4>>4, col4=(f4&15)*4.
    // Consecutive lanes hit consecutive 16B within a row (8 lines/warp-instr).
    uint2 h[8];
    auto ldgcvt = [&](int t) {
#pragma unroll
        for (int it = 0; it < 8; it++) {
            int f4 = it * 256 + tid;
            int row = f4 >> 4;
            int c4 = (f4 & 15) * 4;
            int g = base + t * 128 + row;
            float4 v = make_float4(0.f, 0.f, 0.f, 0.f);
            if (g < n) v = *reinterpret_cast<const float4*>(x + (long long)g * 64 + c4);
            __half2 h0 = __floats2half2_rn(v.x, v.y);
            __half2 h1 = __floats2half2_rn(v.z, v.w);
            h[it].x = *reinterpret_cast<uint32_t*>(&h0);
            h[it].y = *reinterpret_cast<uint32_t*>(&h1);
        }
    };
    auto stsA = [&](int buf) {
#pragma unroll
        for (int it = 0; it < 8; it++) {
            int f4 = it * 256 + tid;
            int row = f4 >> 4;
            int c4 = (f4 & 15) * 4;
            *reinterpret_cast<uint2*>(smA[buf] + row * LDA + c4) = h[it];
        }
    };

    ldgcvt(0);
    stsA(0);
    if (base + 128 < n) ldgcvt(1);
    __syncthreads();

    const uint32_t aB = s2u(smB);

    for (int t = 0; t < TPC; t++) {
        const int r0 = base + t * 128;
        if (r0 >= n) break;

        // stage t+1 (buffer last read by MMA(t-1), safe after prior sync),
        // then prefetch t+2 so its LDGs are in flight during MMA+epilogue.
        if (t + 1 < TPC && r0 + 128 < n) stsA((t + 1) & 1);
        if (t + 2 < TPC && r0 + 256 < n) ldgcvt(t + 2);

        // ---- MMA on smA[t&1]: rows [wbase,wbase+16) x cols [0,64), K=64 ----
        const uint32_t aA = s2u(smA[t & 1]);
        float d[8][4];
#pragma unroll
        for (int nt = 0; nt < 8; nt++)
#pragma unroll
            for (int q = 0; q < 4; q++) d[nt][q] = 0.f;

#pragma unroll
        for (int kk = 0; kk < 4; kk++) {
            uint32_t a[4];
            {
                uint32_t addr = aA + ((wbase + (lane & 15)) * LDA +
                                      kk * 16 + ((lane >> 4) << 3)) * 2;
                ldm_x4(a, addr);
            }
            uint32_t b[16];
#pragma unroll
            for (int np = 0; np < 4; np++) {
                uint32_t addr = aB + ((kk * 16 + (lane & 15)) * LDB +
                                      np * 16 + ((lane >> 4) << 3)) * 2;
                ldm_x4t(b + np * 4, addr);
            }
#pragma unroll
            for (int nt = 0; nt < 8; nt++)
                mma16816(d[nt], a, b + nt * 2);
        }

        // ---- epilogue: +c[seg], softplus, dot Wa ----
        const int g8 = lane >> 2;
        const int l3 = lane & 3;
        float2 wv[8];
#pragma unroll
        for (int nt = 0; nt < 8; nt++)
            wv[nt] = *reinterpret_cast<const float2*>(sWa + nt * 8 + 2 * l3);

#pragma unroll
        for (int hh = 0; hh < 2; hh++) {
            int gr = r0 + wbase + hh * 8 + g8;
            int sg = (gr < n) ? seg_at(nbraw, gr) : 0;
            const float2* cp = reinterpret_cast<const float2*>(d_c + sg * 64);
            float acc = 0.f;
#pragma unroll
            for (int nt = 0; nt < 8; nt++) {
                float2 cc = __ldg(cp + nt * 4 + l3);
                float v0 = d[nt][hh * 2 + 0] + cc.x;
                float v1 = d[nt][hh * 2 + 1] + cc.y;
                acc = fmaf(wv[nt].x, softplusf(v0), acc);
                acc = fmaf(wv[nt].y, softplusf(v1), acc);
            }
            acc += __shfl_xor_sync(0xFFFFFFFFu, acc, 1);
            acc += __shfl_xor_sync(0xFFFFFFFFu, acc, 2);
            if (l3 == 0 && gr < n) out[gr] = acc + sba;
        }

        __syncthreads();
    }
}

// ---------------- kernel 3: warp-per-graph softmax with n-ary bound search ----------------

#define CH 12   // register-cached elements per lane (covers count <= 384)

// first index i in [0,n] with seg(nb[i]) >= val  (warp-collective, 32-way search)
__device__ __forceinline__ int lower_bound_w(const void* nbraw, int n, int val, int lane) {
    int lo = 0, hi = n;           // answer in [lo, hi]
    while (hi - lo > 32) {
        long long d = hi - lo;
        int p = lo + (int)(((long long)(lane + 1) * d) / 33);  // lo < p < hi
        int v = seg_at(nbraw, p);
        unsigned m = __ballot_sync(0xFFFFFFFFu, v < val);
        int cnt = __popc(m);      // sorted -> 'less' lanes form a prefix
        int nlo = (cnt == 0) ? lo : (lo + (int)(((long long)cnt * d) / 33) + 1);
        int nhi = (cnt == 32) ? hi : (lo + (int)(((long long)(cnt + 1) * d) / 33));
        lo = nlo; hi = nhi;
    }
    int p = lo + lane;
    int v = (p < hi && p < n) ? seg_at(nbraw, p) : 0x7FFFFFFF;
    unsigned m = __ballot_sync(0xFFFFFFFFu, (p < hi) && (v < val));
    return lo + __popc(m);
}

__global__ void __launch_bounds__(256)
k_soft(const void* __restrict__ nbraw, float* __restrict__ out, int n, int B) {
    const int b = blockIdx.x * 8 + (threadIdx.x >> 5);
    if (b >= B) return;
    const int lane = threadIdx.x & 31;

    int start = lower_bound_w(nbraw, n, b, lane);
    int end = lower_bound_w(nbraw, n, b + 1, lane);
    if (start >= end) return;

    float vals[CH];
    float lm = __int_as_float(0xFF800000);
#pragma unroll
    for (int c = 0; c < CH; c++) {
        int i = start + lane + c * 32;
        if (i < end) { vals[c] = out[i]; lm = fmaxf(lm, vals[c]); }
    }
    for (int i = start + lane + CH * 32; i < end; i += 32)
        lm = fmaxf(lm, out[i]);

#pragma unroll
    for (int off = 16; off; off >>= 1)
        lm = fmaxf(lm, __shfl_xor_sync(0xFFFFFFFFu, lm, off));
    const float m = lm;

    float ls = 0.f;
#pragma unroll
    for (int c = 0; c < CH; c++) {
        int i = start + lane + c * 32;
        if (i < end) {
            float e = exp2a((vals[c] - m) * 1.4426950408889634f);
            vals[c] = e;
            ls += e;
        }
    }
    for (int i = start + lane + CH * 32; i < end; i += 32)
        ls += exp2a((out[i] - m) * 1.4426950408889634f);

#pragma unroll
    for (int off = 16; off; off >>= 1)
        ls += __shfl_xor_sync(0xFFFFFFFFu, ls, off);
    const float inv = 1.0f / (ls + 1e-16f);

#pragma unroll
    for (int c = 0; c < CH; c++) {
        int i = start + lane + c * 32;
        if (i < end) out[i] = vals[c] * inv;
    }
    for (int i = start + lane + CH * 32; i < end; i += 32)
        out[i] = exp2a((out[i] - m) * 1.4426950408889634f) * inv;
}

// ---------------- launch ----------------

extern "C" void kernel_launch(void* const* d_in, const int* in_sizes, int n_in,
                              void* d_out, int out_size) {
    const float* x = (const float*)d_in[0];
    const void* nb = d_in[1];
    const float* ga = (const float*)d_in[2];
    const float* Wg = (const float*)d_in[3];
    const float* bg = (const float*)d_in[4];
    const float* Wn = (const float*)d_in[5];
    const float* bn = (const float*)d_in[6];
    const float* Wa = (const float*)d_in[7];
    const float* ba = (const float*)d_in[8];
    float* out = (float*)d_out;

    int n = in_sizes[0] / 64;
    if (n > out_size) n = out_size;
    int B = in_sizes[2] / 3;
    if (B > BMAX) B = BMAX;

    k_prep<<<1, 256>>>((const int*)nb, n, Wn);
    k_graph<<<B, 64>>>(ga, Wg, bg, Wn, bn);

    int ctas = (n + TPC * 128 - 1) / (TPC * 128);
    k_main<<<ctas, 256>>>(x, nb, Wa, ba, out, n);

    k_soft<<<(B + 7) / 8, 256>>>(nb, out, n, B);
}